// round 1
// baseline (speedup 1.0000x reference)
#include <cuda_runtime.h>

#define NN 100000
#define NE 1600000
#define NG 1000
#define NODE_IN 32
#define EDGE_IN 16
#define HID 64
#define NL 3
#define EPSBN 1e-5f

// ---------------- device scratch (no allocation allowed) ----------------
__device__ __align__(256) float g_h[NN * HID];      // node features
__device__ __align__(256) float g_hW[NN * HID];     // h@W_h projection / reused as relu(u) buffer
__device__ __align__(256) float g_agg[NN * HID];    // raw scatter sums
__device__ __align__(256) float g_CT[NL * HID * EDGE_IN]; // collapsed edge weights, transposed [l][c][k]
__device__ __align__(256) float g_cbias[NL * HID];  // msg_b + edge_b@W_e
__device__ __align__(256) float g_deg[NN];          // in-degree
__device__ __align__(256) float g_stats[4 * HID];   // [sumE, sumsqE, sumN, sumsqN]
__device__ __align__(256) float g_eaff[2 * HID];    // edge BN affine a,c
__device__ __align__(256) float g_naff[2 * HID];    // node BN affine a,c
__device__ __align__(256) float g_pool[NG * HID];   // graph pooling

// ---------------- f32x2 helpers ----------------
typedef unsigned long long u64t;
__device__ __forceinline__ u64t pk2(float x, float y) {
    u64t r; asm("mov.b64 %0, {%1,%2};" : "=l"(r) : "f"(x), "f"(y)); return r;
}
__device__ __forceinline__ void upk2(u64t v, float& x, float& y) {
    asm("mov.b64 {%0,%1}, %2;" : "=f"(x), "=f"(y) : "l"(v));
}
__device__ __forceinline__ u64t fma2(u64t a, u64t b, u64t c) {
    u64t d; asm("fma.rn.f32x2 %0, %1, %2, %3;" : "=l"(d) : "l"(a), "l"(b), "l"(c)); return d;
}

// ---------------- prep: collapse edge_W into per-layer CT + cbias ----------------
__global__ void k_prep(const float* __restrict__ edgeW, const float* __restrict__ edgeb,
                       const float* __restrict__ msgW, const float* __restrict__ msgb) {
    int l = blockIdx.x;
    const float* We = msgW + l * 96 * HID + 64 * HID; // rows 64..95 of msg_W[l]
    for (int idx = threadIdx.x; idx < HID * EDGE_IN; idx += blockDim.x) {
        int c = idx / EDGE_IN, k = idx % EDGE_IN;
        float s = 0.f;
        for (int t = 0; t < 32; t++) s += edgeW[k * 32 + t] * We[t * HID + c];
        g_CT[l * HID * EDGE_IN + idx] = s; // [c][k] transposed
    }
    for (int c = threadIdx.x; c < HID; c += blockDim.x) {
        float s = msgb[l * HID + c];
        for (int t = 0; t < 32; t++) s += edgeb[t] * We[t * HID + c];
        g_cbias[l * HID + c] = s;
    }
}

// ---------------- zero helpers ----------------
__global__ void k_zero_init() {
    int stride = gridDim.x * blockDim.x;
    for (int i = blockIdx.x * blockDim.x + threadIdx.x; i < NN; i += stride) g_deg[i] = 0.f;
    for (int i = blockIdx.x * blockDim.x + threadIdx.x; i < NG * HID; i += stride) g_pool[i] = 0.f;
}
__global__ void k_zero_layer() {
    int i = blockIdx.x * blockDim.x + threadIdx.x; // 6250*256 = NN*HID/4 exactly
    ((float4*)g_agg)[i] = make_float4(0.f, 0.f, 0.f, 0.f);
    if (blockIdx.x == 0 && threadIdx.x < 4 * HID) g_stats[threadIdx.x] = 0.f;
}

// ---------------- in-degree ----------------
__global__ void k_deg(const int* __restrict__ eidx) {
    int e = blockIdx.x * blockDim.x + threadIdx.x;
    if (e < NE) atomicAdd(&g_deg[eidx[NE + e]], 1.0f);
}

// ---------------- node embedding: h = x @ node_W + node_b ----------------
__global__ __launch_bounds__(256) void k_embed(const float* __restrict__ x,
                                               const float* __restrict__ W,
                                               const float* __restrict__ b) {
    __shared__ float ws[NODE_IN * HID];
    int tid = threadIdx.x, wid = tid >> 5, lane = tid & 31;
    for (int i = tid; i < NODE_IN * HID; i += 256) ws[i] = W[i];
    __syncthreads();
    int n = blockIdx.x * 8 + wid;
    float va = x[n * NODE_IN + lane];
    u64t acc = pk2(b[2 * lane], b[2 * lane + 1]);
#pragma unroll
    for (int k = 0; k < NODE_IN; k++) {
        float a = __shfl_sync(0xffffffffu, va, k);
        u64t w = *(const u64t*)&ws[k * HID + 2 * lane];
        acc = fma2(pk2(a, a), w, acc);
    }
    float o0, o1; upk2(acc, o0, o1);
    ((float2*)(g_h + (size_t)n * HID))[lane] = make_float2(o0, o1);
}

// ---------------- hW = h @ msg_Wh[l] + cbias[l] ----------------
__global__ __launch_bounds__(256) void k_hw(const float* __restrict__ msgW, int layer) {
    __shared__ float ws[HID * HID];
    int tid = threadIdx.x, wid = tid >> 5, lane = tid & 31;
    const float* W = msgW + layer * 96 * HID; // rows 0..63
    for (int i = tid; i < HID * HID; i += 256) ws[i] = W[i];
    __syncthreads();
    int n = blockIdx.x * 8 + wid;
    float va = g_h[n * HID + lane];
    float vb = g_h[n * HID + 32 + lane];
    u64t acc = pk2(g_cbias[layer * HID + 2 * lane], g_cbias[layer * HID + 2 * lane + 1]);
#pragma unroll
    for (int k = 0; k < 32; k++) {
        float a = __shfl_sync(0xffffffffu, va, k);
        acc = fma2(pk2(a, a), *(const u64t*)&ws[k * HID + 2 * lane], acc);
    }
#pragma unroll
    for (int k = 0; k < 32; k++) {
        float a = __shfl_sync(0xffffffffu, vb, k);
        acc = fma2(pk2(a, a), *(const u64t*)&ws[(32 + k) * HID + 2 * lane], acc);
    }
    float o0, o1; upk2(acc, o0, o1);
    ((float2*)(g_hW + (size_t)n * HID))[lane] = make_float2(o0, o1);
}

// ---------------- edge pass: m=relu(hW[src]+ea@C), scatter-add, stats ----------------
#define EK_EPW 8
#define EK_EPB 64
__global__ __launch_bounds__(256) void k_edge(const float* __restrict__ eattr,
                                              const int* __restrict__ eidx, int layer) {
    __shared__ float ea_s[EK_EPB * EDGE_IN]; // 4 KB
    __shared__ float ssum[HID], ssq[HID];
    int tid = threadIdx.x, wid = tid >> 5, lane = tid & 31;
    int ebase = blockIdx.x * EK_EPB;
    // coalesced tile load of edge_attr (64 edges x 16 floats = 256 float4)
    ((float4*)ea_s)[tid] = ((const float4*)(eattr + (size_t)ebase * EDGE_IN))[tid];
    if (tid < HID) { ssum[tid] = 0.f; ssq[tid] = 0.f; }
    // per-lane C columns in registers (k-pair packed, thanks to transposed layout)
    u64t ct0[8], ct1[8];
    {
        const float2* c0p = (const float2*)(g_CT + (size_t)layer * HID * EDGE_IN + (2 * lane) * EDGE_IN);
        const float2* c1p = (const float2*)(g_CT + (size_t)layer * HID * EDGE_IN + (2 * lane + 1) * EDGE_IN);
#pragma unroll
        for (int j = 0; j < 8; j++) {
            float2 t = c0p[j]; ct0[j] = pk2(t.x, t.y);
            t = c1p[j];        ct1[j] = pk2(t.x, t.y);
        }
    }
    __syncthreads();
    float s0 = 0.f, s1 = 0.f, q0 = 0.f, q1 = 0.f;
    const int* srci = eidx;
    const int* dsti = eidx + NE;
#pragma unroll
    for (int j = 0; j < EK_EPW; j++) {
        int le = wid * EK_EPW + j;
        int e = ebase + le;
        int s = srci[e], d = dsti[e];
        float2 hw = ((const float2*)(g_hW + (size_t)s * HID))[lane];
        u64t accA = pk2(0.f, 0.f), accB = pk2(0.f, 0.f);
        const u64t* eap = (const u64t*)(ea_s + le * EDGE_IN);
#pragma unroll
        for (int k = 0; k < 8; k++) {
            u64t a2 = eap[k]; // LDS.64 broadcast of (ea[2k], ea[2k+1])
            accA = fma2(a2, ct0[k], accA);
            accB = fma2(a2, ct1[k], accB);
        }
        float ax, ay, bx, by; upk2(accA, ax, ay); upk2(accB, bx, by);
        float m0 = fmaxf(ax + ay + hw.x, 0.f);
        float m1 = fmaxf(bx + by + hw.y, 0.f);
        float* ap = g_agg + (size_t)d * HID + 2 * lane;
        asm volatile("red.global.add.v2.f32 [%0], {%1, %2};" :: "l"(ap), "f"(m0), "f"(m1) : "memory");
        s0 += m0; s1 += m1;
        q0 = fmaf(m0, m0, q0); q1 = fmaf(m1, m1, q1);
    }
    atomicAdd(&ssum[2 * lane], s0);     atomicAdd(&ssum[2 * lane + 1], s1);
    atomicAdd(&ssq[2 * lane], q0);      atomicAdd(&ssq[2 * lane + 1], q1);
    __syncthreads();
    if (tid < HID) {
        atomicAdd(&g_stats[tid], ssum[tid]);
        atomicAdd(&g_stats[HID + tid], ssq[tid]);
    }
}

// ---------------- BN affine from stats ----------------
__global__ void k_aff(const float* __restrict__ gamma, const float* __restrict__ beta,
                      int layer, float invN, int statoff, int which) {
    int c = threadIdx.x; // 64 threads
    float s = g_stats[statoff + c], q = g_stats[statoff + HID + c];
    float mu = s * invN;
    float var = q * invN - mu * mu;
    float a = gamma[layer * HID + c] * rsqrtf(var + EPSBN);
    float cc = beta[layer * HID + c] - a * mu;
    float* dst = which ? g_naff : g_eaff;
    dst[c] = a; dst[HID + c] = cc;
}

// ---------------- update: r = relu(h@Uh + agg'@Ua + b), node stats ----------------
__global__ __launch_bounds__(256) void k_upd(const float* __restrict__ updW,
                                             const float* __restrict__ updb, int layer) {
    __shared__ float ws[128 * HID]; // 32 KB
    __shared__ float ssum[HID], ssq[HID];
    int tid = threadIdx.x, wid = tid >> 5, lane = tid & 31;
    const float* W = updW + layer * 128 * HID;
    for (int i = tid; i < 128 * HID; i += 256) ws[i] = W[i];
    if (tid < HID) { ssum[tid] = 0.f; ssq[tid] = 0.f; }
    __syncthreads();
    int n = blockIdx.x * 8 + wid;
    float va = g_h[n * HID + lane];
    float vb = g_h[n * HID + 32 + lane];
    float deg = g_deg[n];
    // fold edge-BN affine into aggregate
    float ga = g_eaff[lane] * g_agg[n * HID + lane] + g_eaff[HID + lane] * deg;
    float gb = g_eaff[32 + lane] * g_agg[n * HID + 32 + lane] + g_eaff[HID + 32 + lane] * deg;
    u64t acc = pk2(updb[layer * HID + 2 * lane], updb[layer * HID + 2 * lane + 1]);
#pragma unroll
    for (int k = 0; k < 32; k++) {
        float a = __shfl_sync(0xffffffffu, va, k);
        acc = fma2(pk2(a, a), *(const u64t*)&ws[k * HID + 2 * lane], acc);
    }
#pragma unroll
    for (int k = 0; k < 32; k++) {
        float a = __shfl_sync(0xffffffffu, vb, k);
        acc = fma2(pk2(a, a), *(const u64t*)&ws[(32 + k) * HID + 2 * lane], acc);
    }
#pragma unroll
    for (int k = 0; k < 32; k++) {
        float a = __shfl_sync(0xffffffffu, ga, k);
        acc = fma2(pk2(a, a), *(const u64t*)&ws[(64 + k) * HID + 2 * lane], acc);
    }
#pragma unroll
    for (int k = 0; k < 32; k++) {
        float a = __shfl_sync(0xffffffffu, gb, k);
        acc = fma2(pk2(a, a), *(const u64t*)&ws[(96 + k) * HID + 2 * lane], acc);
    }
    float o0, o1; upk2(acc, o0, o1);
    o0 = fmaxf(o0, 0.f); o1 = fmaxf(o1, 0.f);
    ((float2*)(g_hW + (size_t)n * HID))[lane] = make_float2(o0, o1); // r buffer (reuse g_hW)
    atomicAdd(&ssum[2 * lane], o0);             atomicAdd(&ssum[2 * lane + 1], o1);
    atomicAdd(&ssq[2 * lane], o0 * o0);         atomicAdd(&ssq[2 * lane + 1], o1 * o1);
    __syncthreads();
    if (tid < HID) {
        atomicAdd(&g_stats[2 * HID + tid], ssum[tid]);
        atomicAdd(&g_stats[3 * HID + tid], ssq[tid]);
    }
}

// ---------------- apply node BN affine: h = na*r + nc ----------------
__global__ void k_bnapply() {
    int i = blockIdx.x * blockDim.x + threadIdx.x; // 6250*256 = NN*HID/4 exactly
    int c = (i & 15) * 4;
    float4 r = ((const float4*)g_hW)[i];
    float4 o;
    o.x = g_naff[c + 0] * r.x + g_naff[HID + c + 0];
    o.y = g_naff[c + 1] * r.y + g_naff[HID + c + 1];
    o.z = g_naff[c + 2] * r.z + g_naff[HID + c + 2];
    o.w = g_naff[c + 3] * r.w + g_naff[HID + c + 3];
    ((float4*)g_h)[i] = o;
}

// ---------------- global add pool ----------------
__global__ __launch_bounds__(256) void k_pool(const int* __restrict__ batch) {
    int tid = threadIdx.x, wid = tid >> 5, lane = tid & 31;
    int n = blockIdx.x * 8 + wid;
    int b = batch[n];
    float2 v = ((const float2*)(g_h + (size_t)n * HID))[lane];
    float* ap = g_pool + (size_t)b * HID + 2 * lane;
    asm volatile("red.global.add.v2.f32 [%0], {%1, %2};" :: "l"(ap), "f"(v.x), "f"(v.y) : "memory");
}

// ---------------- readout: out = relu(g@r1+b1)@r2 + b2 ----------------
__global__ __launch_bounds__(256) void k_read(const float* __restrict__ r1W, const float* __restrict__ r1b,
                                              const float* __restrict__ r2W, const float* __restrict__ r2b,
                                              float* __restrict__ out) {
    __shared__ float ws[HID * HID];
    int tid = threadIdx.x, wid = tid >> 5, lane = tid & 31;
    for (int i = tid; i < HID * HID; i += 256) ws[i] = r1W[i];
    __syncthreads();
    int g = blockIdx.x * 8 + wid;
    float va = g_pool[g * HID + lane];
    float vb = g_pool[g * HID + 32 + lane];
    u64t acc = pk2(r1b[2 * lane], r1b[2 * lane + 1]);
#pragma unroll
    for (int k = 0; k < 32; k++) {
        float a = __shfl_sync(0xffffffffu, va, k);
        acc = fma2(pk2(a, a), *(const u64t*)&ws[k * HID + 2 * lane], acc);
    }
#pragma unroll
    for (int k = 0; k < 32; k++) {
        float a = __shfl_sync(0xffffffffu, vb, k);
        acc = fma2(pk2(a, a), *(const u64t*)&ws[(32 + k) * HID + 2 * lane], acc);
    }
    float h0, h1; upk2(acc, h0, h1);
    h0 = fmaxf(h0, 0.f); h1 = fmaxf(h1, 0.f);
    float p = h0 * r2W[2 * lane] + h1 * r2W[2 * lane + 1];
#pragma unroll
    for (int off = 16; off; off >>= 1) p += __shfl_xor_sync(0xffffffffu, p, off);
    if (lane == 0) out[g] = p + r2b[0];
}

// ---------------- launch ----------------
extern "C" void kernel_launch(void* const* d_in, const int* in_sizes, int n_in,
                              void* d_out, int out_size) {
    (void)in_sizes; (void)n_in; (void)out_size;
    const float* x      = (const float*)d_in[0];
    const float* eattr  = (const float*)d_in[1];
    const int*   eidx   = (const int*)d_in[2];
    const int*   batch  = (const int*)d_in[3];
    const float* nodeW  = (const float*)d_in[4];
    const float* nodeb  = (const float*)d_in[5];
    const float* edgeW  = (const float*)d_in[6];
    const float* edgeb  = (const float*)d_in[7];
    const float* msgW   = (const float*)d_in[8];
    const float* msgb   = (const float*)d_in[9];
    const float* msgg   = (const float*)d_in[10];
    const float* msgbe  = (const float*)d_in[11];
    const float* updW   = (const float*)d_in[12];
    const float* updb   = (const float*)d_in[13];
    const float* updg   = (const float*)d_in[14];
    const float* updbe  = (const float*)d_in[15];
    const float* r1W    = (const float*)d_in[16];
    const float* r1b    = (const float*)d_in[17];
    const float* r2W    = (const float*)d_in[18];
    const float* r2b    = (const float*)d_in[19];
    float* out = (float*)d_out;

    k_prep<<<NL, 256>>>(edgeW, edgeb, msgW, msgb);
    k_zero_init<<<256, 256>>>();
    k_deg<<<NE / 256, 256>>>(eidx);
    k_embed<<<NN / 8, 256>>>(x, nodeW, nodeb);

    for (int l = 0; l < NL; l++) {
        k_zero_layer<<<NN * HID / 4 / 256, 256>>>();
        k_hw<<<NN / 8, 256>>>(msgW, l);
        k_edge<<<NE / EK_EPB, 256>>>(eattr, eidx, l);
        k_aff<<<1, 64>>>(msgg, msgbe, l, 1.0f / NE, 0, 0);
        k_upd<<<NN / 8, 256>>>(updW, updb, l);
        k_aff<<<1, 64>>>(updg, updbe, l, 1.0f / NN, 2 * HID, 1);
        k_bnapply<<<NN * HID / 4 / 256, 256>>>();
    }
    k_pool<<<NN / 8, 256>>>(batch);
    k_read<<<NG / 8, 256>>>(r1W, r1b, r2W, r2b, out);
}

// round 2
// speedup vs baseline: 1.0796x; 1.0796x over previous
#include <cuda_runtime.h>

#define NN 100000
#define NE 1600000
#define NG 1000
#define NODE_IN 32
#define EDGE_IN 16
#define HID 64
#define NL 3
#define EPSBN 1e-5f

// ---------------- device scratch (no allocation allowed) ----------------
__device__ __align__(256) float g_h[NN * HID];       // node features r (raw, pre-BN-affine)
__device__ __align__(256) float g_hW[NN * HID];      // h@W_h projection
__device__ __align__(256) float g_agg[NN * HID];     // per-dst message sums (raw)
__device__ __align__(256) float g_CT[NL * HID * EDGE_IN]; // collapsed edge weights, [l][c][k]
__device__ __align__(256) float g_cbias[NL * HID];   // msg_b + edge_b@W_e
__device__ __align__(256) float g_stats[4 * HID];    // [sumE, sumsqE, sumN, sumsqN]
__device__ __align__(256) float g_eaff[2 * HID];     // edge BN affine a,c
__device__ __align__(256) float g_naff[2 * HID];     // node BN affine a,c
__device__ __align__(256) float g_pool[NG * HID];    // graph pooling
// CSR machinery
__device__ __align__(256) int   g_cnt[NN];
__device__ __align__(256) int   g_cur[NN];
__device__ __align__(256) int   g_rowptr[NN + 1];
__device__ __align__(256) int   g_rows[NN];          // per-block exclusive scan
__device__ __align__(256) int   g_bsum[128];
__device__ __align__(256) int   g_boff[128];
__device__ __align__(256) int   g_srcperm[NE];
__device__ __align__(256) int   g_eperm[NE];
__device__ __align__(256) float g_eaperm[(size_t)NE * EDGE_IN]; // 102.4 MB

// ---------------- f32x2 helpers ----------------
typedef unsigned long long u64t;
__device__ __forceinline__ u64t pk2(float x, float y) {
    u64t r; asm("mov.b64 %0, {%1,%2};" : "=l"(r) : "f"(x), "f"(y)); return r;
}
__device__ __forceinline__ void upk2(u64t v, float& x, float& y) {
    asm("mov.b64 {%0,%1}, %2;" : "=f"(x), "=f"(y) : "l"(v));
}
__device__ __forceinline__ u64t fma2(u64t a, u64t b, u64t c) {
    u64t d; asm("fma.rn.f32x2 %0, %1, %2, %3;" : "=l"(d) : "l"(a), "l"(b), "l"(c)); return d;
}

// ---------------- prep: collapse edge_W into per-layer CT + cbias ----------------
__global__ void k_prep(const float* __restrict__ edgeW, const float* __restrict__ edgeb,
                       const float* __restrict__ msgW, const float* __restrict__ msgb) {
    int l = blockIdx.x;
    const float* We = msgW + l * 96 * HID + 64 * HID; // rows 64..95 of msg_W[l]
    for (int idx = threadIdx.x; idx < HID * EDGE_IN; idx += blockDim.x) {
        int c = idx / EDGE_IN, k = idx % EDGE_IN;
        float s = 0.f;
        for (int t = 0; t < 32; t++) s += edgeW[k * 32 + t] * We[t * HID + c];
        g_CT[l * HID * EDGE_IN + idx] = s; // [c][k] transposed
    }
    for (int c = threadIdx.x; c < HID; c += blockDim.x) {
        float s = msgb[l * HID + c];
        for (int t = 0; t < 32; t++) s += edgeb[t] * We[t * HID + c];
        g_cbias[l * HID + c] = s;
    }
}

// ---------------- init: zero counters/stats/pool, identity node affine ----------------
__global__ void k_zero_init() {
    int stride = gridDim.x * blockDim.x;
    int t0 = blockIdx.x * blockDim.x + threadIdx.x;
    for (int i = t0; i < NN; i += stride) { g_cnt[i] = 0; g_cur[i] = 0; }
    for (int i = t0; i < NG * HID; i += stride) g_pool[i] = 0.f;
    if (blockIdx.x == 0) {
        if (threadIdx.x < 4 * HID) g_stats[threadIdx.x] = 0.f;
        if (threadIdx.x < HID) { g_naff[threadIdx.x] = 1.f; g_naff[HID + threadIdx.x] = 0.f; }
    }
}

// ---------------- CSR build ----------------
__global__ void k_hist(const int* __restrict__ eidx) {
    int e = blockIdx.x * blockDim.x + threadIdx.x;
    if (e < NE) atomicAdd(&g_cnt[eidx[NE + e]], 1);
}
__global__ void k_scan1() {
    __shared__ int sh[1024];
    int gid = blockIdx.x * 1024 + threadIdx.x;
    int v = (gid < NN) ? g_cnt[gid] : 0;
    sh[threadIdx.x] = v; __syncthreads();
    for (int off = 1; off < 1024; off <<= 1) {
        int t = (threadIdx.x >= off) ? sh[threadIdx.x - off] : 0;
        __syncthreads();
        sh[threadIdx.x] += t;
        __syncthreads();
    }
    if (gid < NN) g_rows[gid] = sh[threadIdx.x] - v;  // exclusive within block
    if (threadIdx.x == 1023) g_bsum[blockIdx.x] = sh[1023];
}
__global__ void k_scan2(int nblk) {
    __shared__ int sh[128];
    int t = threadIdx.x;
    sh[t] = (t < nblk) ? g_bsum[t] : 0;
    __syncthreads();
    if (t == 0) {
        int run = 0;
        for (int i = 0; i < nblk; i++) { int v = sh[i]; sh[i] = run; run += v; }
    }
    __syncthreads();
    if (t < nblk) g_boff[t] = sh[t];
}
__global__ void k_scan3() {
    int gid = blockIdx.x * 1024 + threadIdx.x;
    if (gid < NN) g_rowptr[gid] = g_rows[gid] + g_boff[blockIdx.x];
    if (gid == 0) g_rowptr[NN] = NE;
}
__global__ void k_scatter(const int* __restrict__ eidx) {
    int e = blockIdx.x * blockDim.x + threadIdx.x;
    if (e < NE) {
        int d = eidx[NE + e];
        int pos = g_rowptr[d] + atomicAdd(&g_cur[d], 1);
        g_srcperm[pos] = eidx[e];
        g_eperm[pos] = e;
    }
}
__global__ void k_permea(const float* __restrict__ eattr) {
    int idx = blockIdx.x * blockDim.x + threadIdx.x; // NE*4 float4 slots
    int pos = idx >> 2, q = idx & 3;
    int e = g_eperm[pos];
    ((float4*)g_eaperm)[idx] = ((const float4*)eattr)[e * 4 + q];
}

// ---------------- node embedding: h = x @ node_W + node_b ----------------
__global__ __launch_bounds__(256) void k_embed(const float* __restrict__ x,
                                               const float* __restrict__ W,
                                               const float* __restrict__ b) {
    __shared__ float ws[NODE_IN * HID];
    int tid = threadIdx.x, wid = tid >> 5, lane = tid & 31;
    for (int i = tid; i < NODE_IN * HID; i += 256) ws[i] = W[i];
    __syncthreads();
    int n = blockIdx.x * 8 + wid;
    float va = x[n * NODE_IN + lane];
    u64t acc = pk2(b[2 * lane], b[2 * lane + 1]);
#pragma unroll
    for (int k = 0; k < NODE_IN; k++) {
        float a = __shfl_sync(0xffffffffu, va, k);
        acc = fma2(pk2(a, a), *(const u64t*)&ws[k * HID + 2 * lane], acc);
    }
    float o0, o1; upk2(acc, o0, o1);
    ((float2*)(g_h + (size_t)n * HID))[lane] = make_float2(o0, o1);
}

// ---------------- hW = bn(h) @ msg_Wh[l] + cbias[l] ----------------
__global__ __launch_bounds__(256) void k_hw(const float* __restrict__ msgW, int layer) {
    __shared__ float ws[HID * HID];
    int tid = threadIdx.x, wid = tid >> 5, lane = tid & 31;
    const float* W = msgW + layer * 96 * HID; // rows 0..63
    for (int i = tid; i < HID * HID; i += 256) ws[i] = W[i];
    __syncthreads();
    int n = blockIdx.x * 8 + wid;
    float va = g_naff[lane] * g_h[n * HID + lane] + g_naff[HID + lane];
    float vb = g_naff[32 + lane] * g_h[n * HID + 32 + lane] + g_naff[HID + 32 + lane];
    u64t acc = pk2(g_cbias[layer * HID + 2 * lane], g_cbias[layer * HID + 2 * lane + 1]);
#pragma unroll
    for (int k = 0; k < 32; k++) {
        float a = __shfl_sync(0xffffffffu, va, k);
        acc = fma2(pk2(a, a), *(const u64t*)&ws[k * HID + 2 * lane], acc);
    }
#pragma unroll
    for (int k = 0; k < 32; k++) {
        float a = __shfl_sync(0xffffffffu, vb, k);
        acc = fma2(pk2(a, a), *(const u64t*)&ws[(32 + k) * HID + 2 * lane], acc);
    }
    float o0, o1; upk2(acc, o0, o1);
    ((float2*)(g_hW + (size_t)n * HID))[lane] = make_float2(o0, o1);
}

// ---------------- edge pass (CSR): warp per dst node, register aggregation ----------------
#define TEW 8
__global__ __launch_bounds__(256) void k_edge(int layer) {
    __shared__ __align__(16) float ea_s[8][TEW * EDGE_IN]; // 8 warps x 512B
    __shared__ float ssum[HID], ssq[HID];
    int tid = threadIdx.x, wid = tid >> 5, lane = tid & 31;
    if (tid < HID) { ssum[tid] = 0.f; ssq[tid] = 0.f; }
    // per-lane C columns in registers (k-pair packed)
    u64t ct0[8], ct1[8];
    {
        const float2* c0p = (const float2*)(g_CT + (size_t)layer * HID * EDGE_IN + (2 * lane) * EDGE_IN);
        const float2* c1p = (const float2*)(g_CT + (size_t)layer * HID * EDGE_IN + (2 * lane + 1) * EDGE_IN);
#pragma unroll
        for (int j = 0; j < 8; j++) {
            float2 t = c0p[j]; ct0[j] = pk2(t.x, t.y);
            t = c1p[j];        ct1[j] = pk2(t.x, t.y);
        }
    }
    __syncthreads();
    int n = blockIdx.x * 8 + wid;
    int beg = g_rowptr[n], end = g_rowptr[n + 1];
    float* easw = ea_s[wid];
    float a0 = 0.f, a1 = 0.f;            // aggregate for this node
    float s0 = 0.f, s1 = 0.f, q0 = 0.f, q1 = 0.f; // BN stats
    int t0 = beg;
    // full tiles of TEW edges
    for (; t0 + TEW <= end; t0 += TEW) {
        ((float4*)easw)[lane] = ((const float4*)g_eaperm)[(size_t)t0 * 4 + lane];
        int msrc = (lane < TEW) ? g_srcperm[t0 + lane] : 0;
        __syncwarp();
        float2 hwv[TEW];
#pragma unroll
        for (int j = 0; j < TEW; j++) {
            int s = __shfl_sync(0xffffffffu, msrc, j);
            hwv[j] = ((const float2*)(g_hW + (size_t)s * HID))[lane];
        }
#pragma unroll
        for (int j = 0; j < TEW; j++) {
            const u64t* eap = (const u64t*)(easw + j * EDGE_IN);
            u64t accA = 0ull, accB = 0ull;
#pragma unroll
            for (int k = 0; k < 8; k++) {
                u64t a2 = eap[k];
                accA = fma2(a2, ct0[k], accA);
                accB = fma2(a2, ct1[k], accB);
            }
            float ax, ay, bx, by; upk2(accA, ax, ay); upk2(accB, bx, by);
            float m0 = fmaxf(ax + ay + hwv[j].x, 0.f);
            float m1 = fmaxf(bx + by + hwv[j].y, 0.f);
            a0 += m0; a1 += m1;
            s0 += m0; s1 += m1;
            q0 = fmaf(m0, m0, q0); q1 = fmaf(m1, m1, q1);
        }
        __syncwarp();
    }
    // tail
    int cnt = end - t0;
    if (cnt > 0) {
        for (int i = lane; i < cnt * 4; i += 32)
            ((float4*)easw)[i] = ((const float4*)g_eaperm)[(size_t)t0 * 4 + i];
        int msrc = (lane < cnt) ? g_srcperm[t0 + lane] : 0;
        __syncwarp();
        for (int j = 0; j < cnt; j++) {
            int s = __shfl_sync(0xffffffffu, msrc, j);
            float2 hw = ((const float2*)(g_hW + (size_t)s * HID))[lane];
            const u64t* eap = (const u64t*)(easw + j * EDGE_IN);
            u64t accA = 0ull, accB = 0ull;
#pragma unroll
            for (int k = 0; k < 8; k++) {
                u64t a2 = eap[k];
                accA = fma2(a2, ct0[k], accA);
                accB = fma2(a2, ct1[k], accB);
            }
            float ax, ay, bx, by; upk2(accA, ax, ay); upk2(accB, bx, by);
            float m0 = fmaxf(ax + ay + hw.x, 0.f);
            float m1 = fmaxf(bx + by + hw.y, 0.f);
            a0 += m0; a1 += m1;
            s0 += m0; s1 += m1;
            q0 = fmaf(m0, m0, q0); q1 = fmaf(m1, m1, q1);
        }
    }
    ((float2*)(g_agg + (size_t)n * HID))[lane] = make_float2(a0, a1);
    atomicAdd(&ssum[2 * lane], s0);     atomicAdd(&ssum[2 * lane + 1], s1);
    atomicAdd(&ssq[2 * lane], q0);      atomicAdd(&ssq[2 * lane + 1], q1);
    __syncthreads();
    if (tid < HID) {
        atomicAdd(&g_stats[tid], ssum[tid]);
        atomicAdd(&g_stats[HID + tid], ssq[tid]);
    }
}

// ---------------- BN affine from stats (and zero stats for next layer) ----------------
__global__ void k_aff(const float* __restrict__ gamma, const float* __restrict__ beta,
                      int layer, float invN, int statoff, int which) {
    int c = threadIdx.x; // 64 threads
    float s = g_stats[statoff + c], q = g_stats[statoff + HID + c];
    float mu = s * invN;
    float var = q * invN - mu * mu;
    float a = gamma[layer * HID + c] * rsqrtf(var + EPSBN);
    float cc = beta[layer * HID + c] - a * mu;
    float* dst = which ? g_naff : g_eaff;
    dst[c] = a; dst[HID + c] = cc;
    g_stats[statoff + c] = 0.f; g_stats[statoff + HID + c] = 0.f;
}

// ---------------- update: r = relu(bn(h)@Uh + bnE(agg)@Ua + b), node stats ----------------
__global__ __launch_bounds__(256) void k_upd(const float* __restrict__ updW,
                                             const float* __restrict__ updb, int layer) {
    __shared__ float ws[128 * HID]; // 32 KB
    __shared__ float ssum[HID], ssq[HID];
    int tid = threadIdx.x, wid = tid >> 5, lane = tid & 31;
    const float* W = updW + layer * 128 * HID;
    for (int i = tid; i < 128 * HID; i += 256) ws[i] = W[i];
    if (tid < HID) { ssum[tid] = 0.f; ssq[tid] = 0.f; }
    __syncthreads();
    int n = blockIdx.x * 8 + wid;
    float va = g_naff[lane] * g_h[n * HID + lane] + g_naff[HID + lane];
    float vb = g_naff[32 + lane] * g_h[n * HID + 32 + lane] + g_naff[HID + 32 + lane];
    float deg = (float)(g_rowptr[n + 1] - g_rowptr[n]);
    float ga = g_eaff[lane] * g_agg[n * HID + lane] + g_eaff[HID + lane] * deg;
    float gb = g_eaff[32 + lane] * g_agg[n * HID + 32 + lane] + g_eaff[HID + 32 + lane] * deg;
    u64t acc = pk2(updb[layer * HID + 2 * lane], updb[layer * HID + 2 * lane + 1]);
#pragma unroll
    for (int k = 0; k < 32; k++) {
        float a = __shfl_sync(0xffffffffu, va, k);
        acc = fma2(pk2(a, a), *(const u64t*)&ws[k * HID + 2 * lane], acc);
    }
#pragma unroll
    for (int k = 0; k < 32; k++) {
        float a = __shfl_sync(0xffffffffu, vb, k);
        acc = fma2(pk2(a, a), *(const u64t*)&ws[(32 + k) * HID + 2 * lane], acc);
    }
#pragma unroll
    for (int k = 0; k < 32; k++) {
        float a = __shfl_sync(0xffffffffu, ga, k);
        acc = fma2(pk2(a, a), *(const u64t*)&ws[(64 + k) * HID + 2 * lane], acc);
    }
#pragma unroll
    for (int k = 0; k < 32; k++) {
        float a = __shfl_sync(0xffffffffu, gb, k);
        acc = fma2(pk2(a, a), *(const u64t*)&ws[(96 + k) * HID + 2 * lane], acc);
    }
    float o0, o1; upk2(acc, o0, o1);
    o0 = fmaxf(o0, 0.f); o1 = fmaxf(o1, 0.f);
    ((float2*)(g_h + (size_t)n * HID))[lane] = make_float2(o0, o1); // raw r (affine applied by readers)
    atomicAdd(&ssum[2 * lane], o0);             atomicAdd(&ssum[2 * lane + 1], o1);
    atomicAdd(&ssq[2 * lane], o0 * o0);         atomicAdd(&ssq[2 * lane + 1], o1 * o1);
    __syncthreads();
    if (tid < HID) {
        atomicAdd(&g_stats[2 * HID + tid], ssum[tid]);
        atomicAdd(&g_stats[3 * HID + tid], ssq[tid]);
    }
}

// ---------------- global add pool (applies final node affine) ----------------
__global__ __launch_bounds__(256) void k_pool(const int* __restrict__ batch) {
    int tid = threadIdx.x, wid = tid >> 5, lane = tid & 31;
    int n = blockIdx.x * 8 + wid;
    int b = batch[n];
    float2 v = ((const float2*)(g_h + (size_t)n * HID))[lane];
    float p0 = g_naff[2 * lane] * v.x + g_naff[HID + 2 * lane];
    float p1 = g_naff[2 * lane + 1] * v.y + g_naff[HID + 2 * lane + 1];
    float* ap = g_pool + (size_t)b * HID + 2 * lane;
    asm volatile("red.global.add.v2.f32 [%0], {%1, %2};" :: "l"(ap), "f"(p0), "f"(p1) : "memory");
}

// ---------------- readout ----------------
__global__ __launch_bounds__(256) void k_read(const float* __restrict__ r1W, const float* __restrict__ r1b,
                                              const float* __restrict__ r2W, const float* __restrict__ r2b,
                                              float* __restrict__ out) {
    __shared__ float ws[HID * HID];
    int tid = threadIdx.x, wid = tid >> 5, lane = tid & 31;
    for (int i = tid; i < HID * HID; i += 256) ws[i] = r1W[i];
    __syncthreads();
    int g = blockIdx.x * 8 + wid;
    float va = g_pool[g * HID + lane];
    float vb = g_pool[g * HID + 32 + lane];
    u64t acc = pk2(r1b[2 * lane], r1b[2 * lane + 1]);
#pragma unroll
    for (int k = 0; k < 32; k++) {
        float a = __shfl_sync(0xffffffffu, va, k);
        acc = fma2(pk2(a, a), *(const u64t*)&ws[k * HID + 2 * lane], acc);
    }
#pragma unroll
    for (int k = 0; k < 32; k++) {
        float a = __shfl_sync(0xffffffffu, vb, k);
        acc = fma2(pk2(a, a), *(const u64t*)&ws[(32 + k) * HID + 2 * lane], acc);
    }
    float h0, h1; upk2(acc, h0, h1);
    h0 = fmaxf(h0, 0.f); h1 = fmaxf(h1, 0.f);
    float p = h0 * r2W[2 * lane] + h1 * r2W[2 * lane + 1];
#pragma unroll
    for (int off = 16; off; off >>= 1) p += __shfl_xor_sync(0xffffffffu, p, off);
    if (lane == 0) out[g] = p + r2b[0];
}

// ---------------- launch ----------------
extern "C" void kernel_launch(void* const* d_in, const int* in_sizes, int n_in,
                              void* d_out, int out_size) {
    (void)in_sizes; (void)n_in; (void)out_size;
    const float* x      = (const float*)d_in[0];
    const float* eattr  = (const float*)d_in[1];
    const int*   eidx   = (const int*)d_in[2];
    const int*   batch  = (const int*)d_in[3];
    const float* nodeW  = (const float*)d_in[4];
    const float* nodeb  = (const float*)d_in[5];
    const float* edgeW  = (const float*)d_in[6];
    const float* edgeb  = (const float*)d_in[7];
    const float* msgW   = (const float*)d_in[8];
    const float* msgb   = (const float*)d_in[9];
    const float* msgg   = (const float*)d_in[10];
    const float* msgbe  = (const float*)d_in[11];
    const float* updW   = (const float*)d_in[12];
    const float* updb   = (const float*)d_in[13];
    const float* updg   = (const float*)d_in[14];
    const float* updbe  = (const float*)d_in[15];
    const float* r1W    = (const float*)d_in[16];
    const float* r1b    = (const float*)d_in[17];
    const float* r2W    = (const float*)d_in[18];
    const float* r2b    = (const float*)d_in[19];
    float* out = (float*)d_out;

    const int nblk = (NN + 1023) / 1024; // 98

    k_prep<<<NL, 256>>>(edgeW, edgeb, msgW, msgb);
    k_zero_init<<<256, 256>>>();
    k_hist<<<NE / 256, 256>>>(eidx);
    k_scan1<<<nblk, 1024>>>();
    k_scan2<<<1, 128>>>(nblk);
    k_scan3<<<nblk, 1024>>>();
    k_scatter<<<NE / 256, 256>>>(eidx);
    k_permea<<<NE * 4 / 256, 256>>>(eattr);
    k_embed<<<NN / 8, 256>>>(x, nodeW, nodeb);

    for (int l = 0; l < NL; l++) {
        k_hw<<<NN / 8, 256>>>(msgW, l);
        k_edge<<<NN / 8, 256>>>(l);
        k_aff<<<1, 64>>>(msgg, msgbe, l, 1.0f / NE, 0, 0);
        k_upd<<<NN / 8, 256>>>(updW, updb, l);
        k_aff<<<1, 64>>>(updg, updbe, l, 1.0f / NN, 2 * HID, 1);
    }
    k_pool<<<NN / 8, 256>>>(batch);
    k_read<<<NG / 8, 256>>>(r1W, r1b, r2W, r2b, out);
}